// round 16
// baseline (speedup 1.0000x reference)
#include <cuda_runtime.h>
#include <cuda_fp16.h>
#include <cstdint>

// ============================================================
// out[b,n] = sum_{c,p} x[b,c,p]*mask[p,c,n]*ro[c,n]
//          = A(256 x 82944) @ W(82944 x 2000),  k = p*64+c
//   A[b,k] = fp16(x[b,c,p])                  (pack kernel)
//   W[k,n] = fp16(mask)*fp16(ro[k&63,n]*1024)  (built on the fly;
//            output scaled by 1/1024)
// R16 (wavefront model, validated on R13/R15 ncu):
//   CTA tile 256m x 128n, 8 warps at 64x64 (4m x 2n):
//   - mask/A traffic amortized over 2x output (1024 wf per
//     256x128 vs R15's 1536)
//   - B fragments via ldmatrix.x4 non-trans on [n][k] rows
//     (SB=40: 16B-aligned rows, conflict-free LDSM; build STS
//     4-way accepted)
//   - 1 CTA/SM, grid 16 x 9 = 144 CTAs = one wave
// GEMM: mma.sync.m16n8k16 f32-accum, KTILE=32.
// ============================================================

constexpr int BB   = 256;
constexpr int CCH  = 64;
constexpr int PPX  = 1296;
constexpr int NN   = 2000;
constexpr int NPAD = 2048;
constexpr long long KT_TOT = 82944;

constexpr int KSPLIT = 9;
constexpr int KSLICE = 9216;                  // 82944/9
constexpr int KTILE  = 32;
constexpr int NKT    = KSLICE / KTILE;        // 288
constexpr int MTILE  = 256;
constexpr int NTILE  = 128;
constexpr int NTX    = 16;

constexpr int SA = 40;                        // A smem stride (halves), 80B rows
constexpr int SB = 40;                        // B smem stride (halves), 80B rows (LDSM-aligned)
constexpr int A_ST = MTILE * SA;              // 10240 halves / stage
constexpr int B_ST = NTILE * SB;              // 5120 halves / stage
constexpr int SM_A_BYTES  = 2 * A_ST * 2;     // 40960
constexpr int SM_B_BYTES  = 2 * B_ST * 2;     // 20480
constexpr int SMEM_TOTAL  = SM_A_BYTES + SM_B_BYTES;  // 61440

// ------------- scratch (device globals; no runtime allocs allowed) ----------
__device__ __half g_Ah[(size_t)BB * KT_TOT];               // 42.5 MB
__device__ float  g_part[(size_t)KSPLIT * BB * NPAD];      // 18.9 MB

// ----------------------------- helpers --------------------------------------
__device__ __forceinline__ uint32_t smem_u32(const void* p) {
    uint32_t a;
    asm("{ .reg .u64 t; cvta.to.shared.u64 t, %1; cvt.u32.u64 %0, t; }"
        : "=r"(a) : "l"(p));
    return a;
}
#define STS_U32(addr, v) \
    asm volatile("st.shared.b32 [%0], %1;" :: "r"(addr), "r"(v) : "memory")
#define CP_A16(dst, src) \
    asm volatile("cp.async.cg.shared.global [%0], [%1], 16;" :: "r"(dst), "l"(src))
#define CP_COMMIT() asm volatile("cp.async.commit_group;" ::: "memory")
#define CP_WAIT0()  asm volatile("cp.async.wait_group 0;" ::: "memory")
#define LDSM4(r0, r1, r2, r3, addr) \
    asm volatile("ldmatrix.sync.aligned.m8n8.x4.shared.b16 {%0,%1,%2,%3}, [%4];" \
        : "=r"(r0), "=r"(r1), "=r"(r2), "=r"(r3) : "r"(addr))
#define MMA16816(d0, d1, d2, d3, a0, a1, a2, a3, b0, b1) \
    asm volatile("mma.sync.aligned.m16n8k16.row.col.f32.f16.f16.f32 " \
        "{%0,%1,%2,%3}, {%4,%5,%6,%7}, {%8,%9}, {%0,%1,%2,%3};" \
        : "+f"(d0), "+f"(d1), "+f"(d2), "+f"(d3) \
        : "r"(a0), "r"(a1), "r"(a2), "r"(a3), "r"(b0), "r"(b1))

// ------------------ dummy kernels (shift ncu capture slot onto gemm) --------
__global__ void warm_a_kernel() {}
__global__ void warm_b_kernel() {}

// ------------------ kernel 1: pack x -> Ah[b][p*64+c] (fp16) ----------------
__global__ void pack_x_kernel(const float* __restrict__ x) {
    __shared__ float s[64][65];
    int b = blockIdx.y;
    int p0 = blockIdx.x * 64;
    int tid = threadIdx.x;
    const float* xb = x + (size_t)b * (CCH * PPX);
    #pragma unroll
    for (int it = 0; it < 16; it++) {
        int t = tid + it * 256;
        int c = t >> 6, i = t & 63, p = p0 + i;
        s[c][i] = (p < PPX) ? xb[c * PPX + p] : 0.f;
    }
    __syncthreads();
    __half* ab = g_Ah + (size_t)b * KT_TOT;
    #pragma unroll
    for (int it = 0; it < 16; it++) {
        int t = tid + it * 256;
        int i = t >> 6, c = t & 63, p = p0 + i;
        if (p < PPX) ab[p * 64 + c] = __float2half_rn(s[c][i]);
    }
}

// ------------------ kernel 2: fused fp16 mma.sync GEMM ----------------------
__global__ void __launch_bounds__(256, 1)
gemm_kernel(const float* __restrict__ mask, const float* __restrict__ ro) {
    extern __shared__ __align__(16) unsigned char smraw[];
    __half* As  = reinterpret_cast<__half*>(smraw);
    __half* Bsm = reinterpret_cast<__half*>(smraw + SM_A_BYTES);

    int tid = threadIdx.x, w = tid >> 5, l = tid & 31;
    int n0 = blockIdx.x * NTILE;
    long long kbase = (long long)blockIdx.z * KSLICE;

    // B-build mapping (R11/R15 interleaved): thread (nq, kq) owns
    // n = n0 + nq + 32q (q=0..3), k rows {2kq, 2kq+1, +16}
    int nq = tid & 31, kq = (tid >> 5) & 7;
    bool valq[4];
    #pragma unroll
    for (int q = 0; q < 4; q++) valq[q] = (n0 + nq + 32 * q) < NN;

    // readout in registers: rr0/rr1[it][q] = half2{ro[c0][n], ro[c0+1][n]}*1024
    __half2 rr0[2][4], rr1[2][4];
    #pragma unroll
    for (int it = 0; it < 2; it++) {
        #pragma unroll
        for (int q = 0; q < 4; q++) {
            int n = n0 + nq + 32 * q;
            bool ok = (n < NN);
            int c0 = 2 * kq + 16 * it;
            float a0 = ok ? ro[(size_t)c0 * NN + n] * 1024.f : 0.f;
            float a1 = ok ? ro[(size_t)(c0 + 1) * NN + n] * 1024.f : 0.f;
            float b0 = ok ? ro[(size_t)(c0 + 32) * NN + n] * 1024.f : 0.f;
            float b1 = ok ? ro[(size_t)(c0 + 33) * NN + n] * 1024.f : 0.f;
            rr0[it][q] = __floats2half2_rn(a0, a1);
            rr1[it][q] = __floats2half2_rn(b0, b1);
        }
    }

    // A cp.async mapping: thread owns row m = tid (64B = 4 x 16B chunks)
    const __half* arow = g_Ah + (size_t)tid * KT_TOT + kbase;
    uint32_t sbase = smem_u32(As);
    uint32_t adst  = sbase + (uint32_t)(tid * (SA * 2));
    uint32_t bbase = smem_u32(Bsm);

    // mrx[(it*2+h)*4 + q] = mask[kt*32 + 2kq + 16it + h][n0 + nq + 32q]
    float mrx[16];
    auto ldmask = [&](int kt) {
        #pragma unroll
        for (int it = 0; it < 2; it++) {
            #pragma unroll
            for (int h = 0; h < 2; h++) {
                long long krow = kbase + (long long)(kt * KTILE + 2 * kq + 16 * it + h);
                const float* rowp = mask + krow * NN + n0 + nq;
                #pragma unroll
                for (int q = 0; q < 4; q++)
                    mrx[(it * 2 + h) * 4 + q] = valq[q] ? rowp[32 * q] : 0.f;
            }
        }
    };

    // build B tile (layout [n][k], stride SB=40): b32 at (n, k0*2) =
    // {W[k0][n], W[k0+1][n]}
    auto buildB_impl = [&](int s, const __half2 (&rp)[2][4]) {
        uint32_t bst = bbase + (uint32_t)(s * (B_ST * 2));
        #pragma unroll
        for (int it = 0; it < 2; it++) {
            int k0 = 2 * kq + 16 * it;
            #pragma unroll
            for (int q = 0; q < 4; q++) {
                int nn = nq + 32 * q;
                __half2 mm = __floats2half2_rn(mrx[(it * 2 + 0) * 4 + q],
                                               mrx[(it * 2 + 1) * 4 + q]);
                __half2 hh = __hmul2(mm, rp[it][q]);
                STS_U32(bst + (uint32_t)(nn * (SB * 2)) + (uint32_t)(k0 * 2),
                        *reinterpret_cast<uint32_t*>(&hh));
            }
        }
    };
    auto buildB = [&](int kt, int s) {
        if (kt & 1) buildB_impl(s, rr1);
        else        buildB_impl(s, rr0);
    };

    auto cpA = [&](int kt, int s) {
        uint32_t d = adst + (uint32_t)(s * (A_ST * 2));
        const __half* src = arow + (size_t)kt * KTILE;
        #pragma unroll
        for (int c4 = 0; c4 < 4; c4++)
            CP_A16(d + c4 * 16, src + c4 * 8);
    };

    // ---------------- prologue ---------------------------------------------
    ldmask(0);
    cpA(0, 0); CP_COMMIT();
    buildB(0, 0);          // ro in regs: no barrier needed before build
    ldmask(1);

    // fragment addressing: warp tile 64(m) x 64(n); 4 m-warps x 2 n-warps
    int wm = (w & 3) * 64, wn = (w >> 2) * 64;
    uint32_t aLdsm = sbase + (uint32_t)(((wm + (l & 15)) * SA + ((l & 16) ? 8 : 0)) * 2);
    // B ldmatrix.x4 (non-trans) on [n][k]: matrix mi = l>>3
    //   -> {n-group: mi>>1, k-half: mi&1}; row = l&7
    int mi = l >> 3, mrow = l & 7;
    uint32_t bFrag = bbase
        + (uint32_t)((wn + 8 * (mi >> 1) + mrow) * (SB * 2))
        + (uint32_t)((mi & 1) * 16);

    float acc[4][8][4];
    #pragma unroll
    for (int i = 0; i < 4; i++)
        #pragma unroll
        for (int j = 0; j < 8; j++)
            #pragma unroll
            for (int q = 0; q < 4; q++) acc[i][j][q] = 0.f;

    // ---------------- main loop (pipelined: MMA(kt) || build(kt+1)) --------
    for (int kt = 0; kt < NKT; kt++) {
        int s = kt & 1;

        CP_WAIT0();          // A(kt) resident
        __syncthreads();     // publish build(kt) STS + A(kt); fence prior readers

        if (kt + 1 < NKT) {
            cpA(kt + 1, s ^ 1); CP_COMMIT();   // into stage read by MMA(kt-1): safe
            buildB(kt + 1, s ^ 1);             // overlaps MMA(kt) below
        }
        if (kt + 2 < NKT) ldmask(kt + 2);      // refill mrx (consumed above)

        // ---- MMA: warp tile 64(m) x 64(n), 2 ksteps of 16 ----------------
        uint32_t aS = aLdsm + (uint32_t)(s * (A_ST * 2));
        uint32_t bS = bFrag + (uint32_t)(s * (B_ST * 2));
        #pragma unroll
        for (int ks = 0; ks < 2; ks++) {
            uint32_t af[4][4];
            #pragma unroll
            for (int i = 0; i < 4; i++)
                LDSM4(af[i][0], af[i][1], af[i][2], af[i][3],
                      aS + (uint32_t)(i * 16 * SA * 2) + (uint32_t)(ks * 32));
            #pragma unroll
            for (int jj = 0; jj < 4; jj++) {
                // x4: {n 16jj..+7, k-lo}, {same n, k-hi},
                //     {n 16jj+8..+15, k-lo}, {same, k-hi}
                uint32_t q0, q1, q2, q3;
                LDSM4(q0, q1, q2, q3,
                      bS + (uint32_t)(jj * 16 * SB * 2) + (uint32_t)(ks * 32));
                #pragma unroll
                for (int i = 0; i < 4; i++) {
                    MMA16816(acc[i][2 * jj][0], acc[i][2 * jj][1],
                             acc[i][2 * jj][2], acc[i][2 * jj][3],
                             af[i][0], af[i][1], af[i][2], af[i][3], q0, q1);
                    MMA16816(acc[i][2 * jj + 1][0], acc[i][2 * jj + 1][1],
                             acc[i][2 * jj + 1][2], acc[i][2 * jj + 1][3],
                             af[i][0], af[i][1], af[i][2], af[i][3], q2, q3);
                }
            }
        }
    }

    // ---- epilogue: fp32 partials ------------------------------------------
    float* __restrict__ part = g_part + (size_t)blockIdx.z * BB * NPAD;
    int r0 = l >> 2, cq = 2 * (l & 3);
    #pragma unroll
    for (int i = 0; i < 4; i++) {
        #pragma unroll
        for (int j = 0; j < 8; j++) {
            int m = wm + 16 * i + r0;
            int n = n0 + wn + 8 * j + cq;
            *reinterpret_cast<float2*>(part + (size_t)m * NPAD + n) =
                make_float2(acc[i][j][0], acc[i][j][1]);
            *reinterpret_cast<float2*>(part + (size_t)(m + 8) * NPAD + n) =
                make_float2(acc[i][j][2], acc[i][j][3]);
        }
    }
}

// ------------------ kernel 3: reduce partials -> out (x 1/1024) -------------
__global__ void reduce_kernel(float* __restrict__ out) {
    int id = blockIdx.x * 256 + threadIdx.x;          // id indexes (b, n4)
    int b = id / (NPAD / 4), n4 = id % (NPAD / 4);
    if (b >= BB) return;
    int n = n4 * 4;
    float4 s = make_float4(0.f, 0.f, 0.f, 0.f);
    #pragma unroll
    for (int ks = 0; ks < KSPLIT; ks++) {
        const float4 v = *reinterpret_cast<const float4*>(
            g_part + (size_t)ks * BB * NPAD + (size_t)b * NPAD + n);
        s.x += v.x; s.y += v.y; s.z += v.z; s.w += v.w;
    }
    const float inv = 1.f / 1024.f;
    float* o = out + (size_t)b * NN;
    if (n + 3 < NN) {
        o[n] = s.x * inv; o[n + 1] = s.y * inv; o[n + 2] = s.z * inv; o[n + 3] = s.w * inv;
    } else {
        if (n < NN)     o[n]     = s.x * inv;
        if (n + 1 < NN) o[n + 1] = s.y * inv;
        if (n + 2 < NN) o[n + 2] = s.z * inv;
        if (n + 3 < NN) o[n + 3] = s.w * inv;
    }
}

// ------------------------------- host ---------------------------------------
extern "C" void kernel_launch(void* const* d_in, const int* in_sizes, int n_in,
                              void* d_out, int out_size) {
    const float* x = nullptr;
    const float* mw = nullptr;
    const float* ro = nullptr;
    for (int i = 0; i < n_in; i++) {
        long long sz = in_sizes[i];
        if (sz == (long long)BB * CCH * PPX)      x  = (const float*)d_in[i];
        else if (sz == (long long)PPX * CCH * NN) mw = (const float*)d_in[i];
        else if (sz == (long long)CCH * NN)       ro = (const float*)d_in[i];
    }

    cudaFuncSetAttribute(gemm_kernel, cudaFuncAttributeMaxDynamicSharedMemorySize,
                         SMEM_TOTAL);

    warm_a_kernel<<<1, 32>>>();
    warm_b_kernel<<<1, 32>>>();
    pack_x_kernel<<<dim3(21, BB), 256>>>(x);
    gemm_kernel<<<dim3(NTX, 1, KSPLIT), 256, SMEM_TOTAL>>>(mw, ro);
    reduce_kernel<<<(BB * (NPAD / 4) + 255) / 256, 256>>>((float*)d_out);
}